// round 7
// baseline (speedup 1.0000x reference)
#include <cuda_runtime.h>

#define H 128
#define W 128
#define NS 8
#define TY 16
#define SROWS 20           // TY + 4 (sy baked in)
#define SCOLS 132          // W + 4 (sx baked in); 33 float4 groups
#define NSLOT (SROWS * 33) // 660 float4 staging slots

__global__ void __launch_bounds__(128, 8)
shifted_conv_kernel(const float* __restrict__ tens,
                    const float* __restrict__ filters,
                    const int* __restrict__ shifts,
                    float* __restrict__ out)
{
    __shared__ __align__(16) float s_t[SROWS][SCOLS];
    __shared__ float s_f[NS * 25];
    __shared__ int   s_sh[NS * 2];

    const int n    = blockIdx.x;        // 0..255 (B*C)
    const int y0   = blockIdx.y * TY;   // 0..112 step 16
    const int tid  = threadIdx.x;
    const int lane = tid & 31;
    const int wrp  = tid >> 5;

    for (int i = tid; i < NS * 25; i += 128) s_f[i] = filters[i];
    if (tid < NS * 2) s_sh[tid] = shifts[tid];
    __syncthreads();                    // shifts/filters visible

    const float* inp  = tens + (size_t)n * (H * W);
    float*       outb = out  + (size_t)n * (NS * H * W);

    #pragma unroll 1
    for (int s = 0; s < NS; ++s) {
        const int sy = s_sh[2 * s + 0];
        const int sx = s_sh[2 * s + 1];

        // Stage shifted tile: s_t[r][c] = x[y0 + r - sy][c - sx], zero OOB.
        // Then out[y0+ry][x] = sum_{i,j} F[i][j] * s_t[ry+i][x+j].
        for (int i = tid; i < NSLOT; i += 128) {
            int r   = i / 33;
            int g   = i - r * 33;
            int gy  = y0 + r - sy;
            int gx0 = 4 * g - sx;
            float4 v = make_float4(0.f, 0.f, 0.f, 0.f);
            if (gy >= 0 && gy < H) {
                const float* row = inp + gy * W;
                if (gx0 >= 0 && gx0 + 3 < W) {
                    v.x = row[gx0]; v.y = row[gx0 + 1];
                    v.z = row[gx0 + 2]; v.w = row[gx0 + 3];
                } else {
                    if (gx0     >= 0 && gx0     < W) v.x = row[gx0];
                    if (gx0 + 1 >= 0 && gx0 + 1 < W) v.y = row[gx0 + 1];
                    if (gx0 + 2 >= 0 && gx0 + 2 < W) v.z = row[gx0 + 2];
                    if (gx0 + 3 >= 0 && gx0 + 3 < W) v.w = row[gx0 + 3];
                }
            }
            *(float4*)&s_t[r][4 * g] = v;
        }

        // Scalar filter taps in registers (25 regs, no pairing constraints).
        float F[25];
        #pragma unroll
        for (int t = 0; t < 25; ++t) F[t] = s_f[s * 25 + t];

        __syncthreads();                // tile staged

        // Thread computes 4 rows x 4 cols. Window = 2 aligned LDS.128/row.
        float acc[4][4];
        #pragma unroll
        for (int yy = 0; yy < 4; ++yy)
            #pragma unroll
            for (int d = 0; d < 4; ++d) acc[yy][d] = 0.f;

        const int r0 = wrp * 4;
        #pragma unroll
        for (int k = 0; k < 8; ++k) {
            const float* rp = &s_t[r0 + k][4 * lane];
            float4 a = *(const float4*)rp;        // w[0..3]
            float4 b = *(const float4*)(rp + 4);  // w[4..7]
            float w[8] = {a.x, a.y, a.z, a.w, b.x, b.y, b.z, b.w};
            #pragma unroll
            for (int yy = 0; yy < 4; ++yy) {
                const int i = k - yy;             // compile-time after unroll
                if (i >= 0 && i < 5) {
                    #pragma unroll
                    for (int d = 0; d < 4; ++d) {
                        #pragma unroll
                        for (int j = 0; j < 5; ++j)
                            acc[yy][d] = fmaf(F[i * 5 + j], w[d + j], acc[yy][d]);
                    }
                }
            }
        }

        float* ops = outb + (size_t)s * (H * W)
                          + (size_t)(y0 + r0) * W + 4 * lane;
        #pragma unroll
        for (int yy = 0; yy < 4; ++yy)
            *(float4*)(ops + yy * W) =
                make_float4(acc[yy][0], acc[yy][1], acc[yy][2], acc[yy][3]);

        __syncthreads();                // protect tile before next restage
    }
}

extern "C" void kernel_launch(void* const* d_in, const int* in_sizes, int n_in,
                              void* d_out, int out_size)
{
    const float* tens    = (const float*)d_in[0];
    const float* filters = (const float*)d_in[1];
    const int*   shifts  = (const int*)d_in[2];
    float*       out     = (float*)d_out;

    dim3 grid(256, H / TY);   // 2048 blocks
    shifted_conv_kernel<<<grid, 128>>>(tens, filters, shifts, out);
}

// round 8
// speedup vs baseline: 1.4142x; 1.4142x over previous
#include <cuda_runtime.h>

#define H 128
#define W 128
#define NS 8
#define TY 16
#define SROWS (TY + 8)   // 24
#define SCOLS 136        // 128 + 8 halo; even => 8B row alignment holds

__global__ void __launch_bounds__(128)
shifted_conv_kernel(const float* __restrict__ tens,
                    const float* __restrict__ filters,
                    const int* __restrict__ shifts,
                    float* __restrict__ out)
{
    __shared__ __align__(16) float s_a[SROWS][SCOLS];   // x[c]
    __shared__ __align__(16) float s_b[SROWS][SCOLS];   // x[c+1]
    __shared__ float s_f[NS * 25];
    __shared__ int   s_sh[NS * 2];

    const int n    = blockIdx.x;        // 0..255 (B*C)
    const int y0   = blockIdx.y * TY;   // 0..112 step 16
    const int tid  = threadIdx.x;
    const int lane = tid & 31;
    const int wrp  = tid >> 5;

    for (int i = tid; i < NS * 25; i += 128) s_f[i] = filters[i];
    if (tid < NS * 2) s_sh[tid] = shifts[tid];

    // Stage input strip once (4-halo, zero-padded), in two copies offset by 1
    // so any 8-wide window has an 8B-aligned base in one of the copies.
    const float* inp = tens + (size_t)n * (H * W);
    for (int idx = tid; idx < SROWS * SCOLS; idx += 128) {
        int r  = idx / SCOLS;
        int c  = idx - r * SCOLS;
        int gy = y0 - 4 + r;
        int gx = c - 4;
        float v = 0.0f;
        if (gy >= 0 && gy < H && gx >= 0 && gx < W)
            v = inp[gy * W + gx];
        s_a[r][c] = v;
        if (c > 0) s_b[r][c - 1] = v;
    }
    for (int r = tid; r < SROWS; r += 128) s_b[r][SCOLS - 1] = 0.0f;
    __syncthreads();

    const int ybase = wrp * 4;          // 4 output rows per warp
    const int xo    = 4 * lane;         // 4 output cols per lane
    float* outw = out + (size_t)n * (NS * H * W)
                      + (size_t)(y0 + ybase) * W + xo;

    #pragma unroll 1
    for (int s = 0; s < NS; ++s) {
        const int sy = s_sh[2 * s + 0];
        const int sx = s_sh[2 * s + 1];

        // Scalar filter taps: 25 plain regs, no pairing constraints.
        float F[25];
        #pragma unroll
        for (int t = 0; t < 25; ++t) F[t] = s_f[s * 25 + t];

        const int rowbase = ybase + 4 - sy;     // [0, 16]
        const int col0    = xo + 4 - sx;        // window start, in [0, 128]

        // w[t] = x_pad[col0 + t]; 8B-aligned base regardless of sx parity:
        //   sx even -> col0 even -> s_a[col0]
        //   sx odd  -> col0 odd  -> s_b[col0-1]   (s_b[i] = x[i+1])
        const float* base = (sx & 1) ? &s_b[rowbase][col0 - 1]
                                     : &s_a[rowbase][col0];

        float acc[4][4];
        #pragma unroll
        for (int yy = 0; yy < 4; ++yy)
            #pragma unroll
            for (int d = 0; d < 4; ++d) acc[yy][d] = 0.f;

        #pragma unroll
        for (int k = 0; k < 8; ++k) {
            const float2* rp = (const float2*)(base + k * SCOLS);
            float2 a0 = rp[0], a1 = rp[1], a2 = rp[2], a3 = rp[3];
            // LDS.64 halves are individually addressable scalars: no MOVs.
            float w[8] = {a0.x, a0.y, a1.x, a1.y, a2.x, a2.y, a3.x, a3.y};
            #pragma unroll
            for (int yy = 0; yy < 4; ++yy) {
                const int i = k - yy;           // compile-time after unroll
                if (i >= 0 && i < 5) {
                    #pragma unroll
                    for (int d = 0; d < 4; ++d) {
                        #pragma unroll
                        for (int j = 0; j < 5; ++j)
                            acc[yy][d] = fmaf(F[i * 5 + j], w[d + j], acc[yy][d]);
                    }
                }
            }
        }

        float* ops = outw + (size_t)s * (H * W);
        #pragma unroll
        for (int yy = 0; yy < 4; ++yy)
            *(float4*)(ops + yy * W) =
                make_float4(acc[yy][0], acc[yy][1], acc[yy][2], acc[yy][3]);
    }
}

extern "C" void kernel_launch(void* const* d_in, const int* in_sizes, int n_in,
                              void* d_out, int out_size)
{
    const float* tens    = (const float*)d_in[0];
    const float* filters = (const float*)d_in[1];
    const int*   shifts  = (const int*)d_in[2];
    float*       out     = (float*)d_out;

    dim3 grid(256, H / TY);   // 2048 blocks
    shifted_conv_kernel<<<grid, 128>>>(tens, filters, shifts, out);
}